// round 13
// baseline (speedup 1.0000x reference)
#include <cuda_runtime.h>
#include <cuda_fp16.h>
#include <cstdint>

#define BB 2048
#define TT 512
#define DD 178
#define HH 5
#define NG 20
#define THR 512
#define LSTM_CTAS 16
#define GEMM_CTAS 1024
#define HALF_BYTES (64 * DD * 4)        // 45568
#define CHUNK_BYTES (2 * HALF_BYTES)    // 91136

typedef unsigned long long ull;

// fp16 gate pre-activations [b][t][j][i,f,g,o]; bias folded; i,f,o pre-scaled 0.5
__device__ __half g_xg[(size_t)BB * TT * NG];
__device__ int g_flag[GEMM_CTAS];

#define SO_TMA0 0
#define SO_TMA1 8
#define SO_BF   16                       // 18432 B
#define SO_RED  18448                    // 128*24*4 = 12288
#define SO_S0   31744
#define SO_S1   (31744 + CHUNK_BYTES)
#define SM_TOT  (SO_S1 + CHUNK_BYTES)    // 214016

__device__ __forceinline__ uint32_t bf2(float hi, float lo) {
    uint32_t r; asm("cvt.rn.bf16x2.f32 %0, %1, %2;" : "=r"(r) : "f"(hi), "f"(lo)); return r;
}
__device__ __forceinline__ uint32_t h2pack(float lo, float hi) {
    uint32_t r; asm("cvt.rn.f16x2.f32 %0, %1, %2;" : "=r"(r) : "f"(hi), "f"(lo)); return r;
}
__device__ __forceinline__ void cvt_hl(float vx, float vy, uint32_t& h, uint32_t& l) {
    h = bf2(vy, vx);
    float hx = __uint_as_float(h << 16);
    float hy = __uint_as_float(h & 0xffff0000u);
    l = bf2(vy - hy, vx - hx);
}
__device__ __forceinline__ void mma16816(float& d0, float& d1, float& d2, float& d3,
                                         uint32_t a0, uint32_t a1, uint32_t a2, uint32_t a3,
                                         uint32_t b0, uint32_t b1) {
    asm volatile("mma.sync.aligned.m16n8k16.row.col.f32.bf16.bf16.f32 "
                 "{%0,%1,%2,%3}, {%4,%5,%6,%7}, {%8,%9}, {%0,%1,%2,%3};"
                 : "+f"(d0), "+f"(d1), "+f"(d2), "+f"(d3)
                 : "r"(a0), "r"(a1), "r"(a2), "r"(a3), "r"(b0), "r"(b1));
}
__device__ __forceinline__ float tanhap(float xv) {
    float r; asm("tanh.approx.f32 %0, %1;" : "=f"(r) : "f"(xv)); return r;
}
__device__ __forceinline__ void mbar_wait(uint32_t mbar, uint32_t parity) {
    asm volatile(
        "{\n\t.reg .pred P;\nW%=:\n\t"
        "mbarrier.try_wait.parity.acquire.cta.shared::cta.b64 P, [%0], %1, 0x989680;\n\t"
        "@P bra D%=;\n\tbra W%=;\nD%=:\n\t}"
        :: "r"(mbar), "r"(parity) : "memory");
}
__device__ __forceinline__ int ld_acq(const int* p) {
    int v; asm volatile("ld.acquire.gpu.global.u32 %0, [%1];" : "=r"(v) : "l"(p)); return v;
}

extern "C" __global__ void zero_flags() {
    g_flag[blockIdx.x * 256 + threadIdx.x] = 0;
}

// ===========================================================================
// Fused kernel. bid < 16: LSTM consumers. bid >= 16: GEMM producers.
// GEMM: k-split across warp-groups (0: ktiles 0-5 + bias + store;
// 1: ktiles 6-11 -> smem partials). A hi/lo + B hi/lo, 3 MMA passes
// (Ah*Bh + Ah*Bl + Al*Bh) — the R10 precision scheme.
// ===========================================================================
extern "C" __global__ void __launch_bounds__(THR, 1)
fused(const float* __restrict__ x, const float* __restrict__ w_ih,
      const float* __restrict__ b_ih, const float* __restrict__ b_hh,
      const float* __restrict__ w_hh, const float* __restrict__ w_fc,
      const float* __restrict__ b_fc, float* __restrict__ out) {
    extern __shared__ char smem[];
    const int tid = threadIdx.x;
    const int lane = tid & 31;

    if (blockIdx.x >= LSTM_CTAS) {
        // ------------------- GEMM producer -------------------
        const int c = blockIdx.x - LSTM_CTAS;
        const int krange = c >> 7;
        const int bg = c & 127;
        const size_t tbase = (size_t)krange * 64;

        const uint32_t smb = (uint32_t)__cvta_generic_to_shared(smem);
        const uint32_t mbar0 = smb + SO_TMA0, mbar1 = smb + SO_TMA1;
        const int grp = tid >> 8;             // k-half
        const int w8  = (tid >> 5) & 7;
        const int gq = lane >> 2, tq = lane & 3;
        const int r1 = w8 * 16 + gq;          // row 0..127

        uint2* bfrag = (uint2*)(smem + SO_BF);
        float* red = (float*)(smem + SO_RED);

        for (int idx = tid; idx < 12 * 3 * 32; idx += THR) {
            int l = idx & 31, nt = (idx >> 5) % 3, kt = idx / 96;
            int n = nt * 8 + (l >> 2);
            int k = kt * 16 + 2 * (l & 3);
            float w0 = 0, w1 = 0, w2 = 0, w3 = 0;
            if (n < NG) {
                int cc = n & 3, j = n >> 2;
                float s = (cc == 2) ? 1.0f : 0.5f;
                const float* wr = w_ih + (cc * 5 + j) * DD;
                if (k     < DD) w0 = s * wr[k];
                if (k + 1 < DD) w1 = s * wr[k + 1];
                if (k + 8 < DD) w2 = s * wr[k + 8];
                if (k + 9 < DD) w3 = s * wr[k + 9];
            }
            uint32_t b0h, b0l, b1h, b1l;
            cvt_hl(w0, w1, b0h, b0l);
            cvt_hl(w2, w3, b1h, b1l);
            bfrag[(((kt * 3 + nt) * 2 + 0) * 32) + l] = make_uint2(b0h, b1h);
            bfrag[(((kt * 3 + nt) * 2 + 1) * 32) + l] = make_uint2(b0l, b1l);
        }

        float bias0[3], bias1[3];
#pragma unroll
        for (int nt = 0; nt < 3; ++nt) {
            int n0 = nt * 8 + 2 * tq;
            bias0[nt] = bias1[nt] = 0.0f;
            if (grp == 0 && n0 < NG) {
                int cc = n0 & 3, j = n0 >> 2;
                float s = (cc == 2) ? 1.0f : 0.5f;
                bias0[nt] = s * (b_ih[cc * 5 + j] + b_hh[cc * 5 + j]);
                cc = (n0 + 1) & 3; j = (n0 + 1) >> 2;
                s = (cc == 2) ? 1.0f : 0.5f;
                bias1[nt] = s * (b_ih[cc * 5 + j] + b_hh[cc * 5 + j]);
            }
        }

        if (tid == 0) {
            asm volatile("mbarrier.init.shared.b64 [%0], 1;" :: "r"(mbar0));
            asm volatile("mbarrier.init.shared.b64 [%0], 1;" :: "r"(mbar1));
            asm volatile("fence.proxy.async.shared::cta;" ::: "memory");
        }
        __syncthreads();

        ull pol;
        asm("createpolicy.fractional.L2::evict_first.b64 %0, 1.0;" : "=l"(pol));

        auto issue = [&](int ch) {
            uint32_t mb  = (ch & 1) ? mbar1 : mbar0;
            uint32_t dst = smb + ((ch & 1) ? SO_S1 : SO_S0);
            int b0 = bg * 16 + ch * 2;
            const char* s0 = (const char*)(x + ((size_t)b0 * TT + tbase) * DD);
            const char* s1 = (const char*)(x + ((size_t)(b0 + 1) * TT + tbase) * DD);
            asm volatile("mbarrier.arrive.expect_tx.shared.b64 _, [%0], %1;"
                         :: "r"(mb), "r"((uint32_t)CHUNK_BYTES));
            asm volatile(
                "cp.async.bulk.shared::cluster.global.mbarrier::complete_tx::bytes"
                ".L2::cache_hint [%0], [%1], %2, [%3], %4;"
                :: "r"(dst), "l"(s0), "r"((uint32_t)HALF_BYTES), "r"(mb), "l"(pol)
                : "memory");
            asm volatile(
                "cp.async.bulk.shared::cluster.global.mbarrier::complete_tx::bytes"
                ".L2::cache_hint [%0], [%1], %2, [%3], %4;"
                :: "r"(dst + HALF_BYTES), "l"(s1), "r"((uint32_t)HALF_BYTES),
                   "r"(mb), "l"(pol)
                : "memory");
        };
        if (tid == 0) { issue(0); issue(1); }

        for (int ch = 0; ch < 8; ++ch) {
            mbar_wait((ch & 1) ? mbar1 : mbar0, (uint32_t)((ch >> 1) & 1));
            const float* stage = (const float*)(smem + ((ch & 1) ? SO_S1 : SO_S0));
            const float* pr = stage + r1 * DD;

            float d[3][4];
#pragma unroll
            for (int nt = 0; nt < 3; ++nt) {
                d[nt][0] = bias0[nt]; d[nt][1] = bias1[nt];
                d[nt][2] = bias0[nt]; d[nt][3] = bias1[nt];
            }
#pragma unroll
            for (int kt = 0; kt < 6; ++kt) {
                int ktg = grp * 6 + kt;
                int k0 = ktg * 16 + 2 * tq;
                bool v0 = (k0 <= DD - 2);
                bool v2 = (k0 + 8 <= DD - 2);
                float2 z = make_float2(0.0f, 0.0f);
                float2 A0 = v0 ? *(const float2*)(pr + k0)              : z;
                float2 A1 = v0 ? *(const float2*)(pr + 8 * DD + k0)     : z;
                float2 A2 = v2 ? *(const float2*)(pr + k0 + 8)          : z;
                float2 A3 = v2 ? *(const float2*)(pr + 8 * DD + k0 + 8) : z;
                uint32_t ah0, al0, ah1, al1, ah2, al2, ah3, al3;
                cvt_hl(A0.x, A0.y, ah0, al0);
                cvt_hl(A1.x, A1.y, ah1, al1);
                cvt_hl(A2.x, A2.y, ah2, al2);
                cvt_hl(A3.x, A3.y, ah3, al3);
#pragma unroll
                for (int nt = 0; nt < 3; ++nt) {
                    uint2 BH = bfrag[(((ktg * 3 + nt) * 2 + 0) * 32) + lane];
                    uint2 BL = bfrag[(((ktg * 3 + nt) * 2 + 1) * 32) + lane];
                    mma16816(d[nt][0], d[nt][1], d[nt][2], d[nt][3],
                             ah0, ah1, ah2, ah3, BH.x, BH.y);
                    mma16816(d[nt][0], d[nt][1], d[nt][2], d[nt][3],
                             ah0, ah1, ah2, ah3, BL.x, BL.y);
                    mma16816(d[nt][0], d[nt][1], d[nt][2], d[nt][3],
                             al0, al1, al2, al3, BH.x, BH.y);
                }
            }

            if (grp == 1) {
#pragma unroll
                for (int nt = 0; nt < 3; ++nt) {
                    int n0 = nt * 8 + 2 * tq;
                    *(float2*)&red[r1 * 24 + n0]       = make_float2(d[nt][0], d[nt][1]);
                    *(float2*)&red[(r1 + 8) * 24 + n0] = make_float2(d[nt][2], d[nt][3]);
                }
            }
            __syncthreads();
            if (tid == 0 && ch + 2 < 8) issue(ch + 2);

            if (grp == 0) {
                int b = bg * 16 + ch * 2 + (r1 >> 6);
                int t = krange * 64 + (r1 & 63);
                size_t grow = (size_t)b * TT + t;
#pragma unroll
                for (int nt = 0; nt < 3; ++nt) {
                    int n0 = nt * 8 + 2 * tq;
                    float2 p0 = *(const float2*)&red[r1 * 24 + n0];
                    float2 p1 = *(const float2*)&red[(r1 + 8) * 24 + n0];
                    if (n0 < NG) {
                        *(uint32_t*)((char*)g_xg + grow * 40 + n0 * 2) =
                            h2pack(d[nt][0] + p0.x, d[nt][1] + p0.y);
                        *(uint32_t*)((char*)g_xg + (grow + 8) * 40 + n0 * 2) =
                            h2pack(d[nt][2] + p1.x, d[nt][3] + p1.y);
                    }
                }
            }
            __syncthreads();
        }
        __threadfence();
        __syncthreads();
        if (tid == 0)
            asm volatile("st.release.gpu.global.u32 [%0], %1;"
                         :: "l"(&g_flag[c]), "r"(1) : "memory");
        return;
    }

    // ------------------- LSTM consumer (unchanged) -------------------
    const int w    = blockIdx.x * 16 + (tid >> 5);
    const int j0   = lane & 7;
    const int j    = (j0 < HH) ? j0 : 0;
    const int gidx = w * 4 + (lane >> 3);
    const int seqA = 2 * gidx, seqB = seqA + 1;
    const int bgf  = w >> 1;

    float wi[HH], wf[HH], wg[HH], wo[HH];
#pragma unroll
    for (int m = 0; m < HH; ++m) {
        wi[m] = 0.5f * w_hh[j * HH + m];
        wf[m] = 0.5f * w_hh[(HH + j) * HH + m];
        wg[m] =        w_hh[(2 * HH + j) * HH + m];
        wo[m] = 0.5f * w_hh[(3 * HH + j) * HH + m];
    }

    const uint2* gpA = (const uint2*)((const char*)g_xg + (size_t)seqA * TT * 40) + j;
    const uint2* gpB = (const uint2*)((const char*)g_xg + (size_t)seqB * TT * 40) + j;

    float cA = 0.0f, hA = 0.0f, cB = 0.0f, hB = 0.0f;
    float hvA[HH], hvB[HH];
#pragma unroll
    for (int m = 0; m < HH; ++m) { hvA[m] = 0.0f; hvB[m] = 0.0f; }
    const int base = lane & ~7;

    for (int k = 0; k < 8; ++k) {
        const int* fp = &g_flag[k * 128 + bgf];
        if (lane == 0) { while (ld_acq(fp) == 0) __nanosleep(128); }
        __syncwarp();
        (void)ld_acq(fp);

        const int t0 = k * 64;
        uint2 rA[8], rB[8];
#pragma unroll
        for (int p = 0; p < 8; ++p) {
            rA[p] = gpA[(size_t)(t0 + p) * 5];
            rB[p] = gpB[(size_t)(t0 + p) * 5];
        }

        for (int p0 = 0; p0 < 64; p0 += 8) {
#pragma unroll
            for (int pp = 0; pp < 8; ++pp) {
                uint2 curA = rA[pp], curB = rB[pp];
                if (p0 + pp + 8 < 64) {
                    int tn = t0 + p0 + pp + 8;
                    rA[pp] = gpA[(size_t)tn * 5];
                    rB[pp] = gpB[(size_t)tn * 5];
                }
                float2 ifA = __half22float2(*(const __half2*)&curA.x);
                float2 goA = __half22float2(*(const __half2*)&curA.y);
                float2 ifB = __half22float2(*(const __half2*)&curB.x);
                float2 goB = __half22float2(*(const __half2*)&curB.y);

                float piA = ifA.x, pfA = ifA.y, pgA = goA.x, poA = goA.y;
                float piB = ifB.x, pfB = ifB.y, pgB = goB.x, poB = goB.y;
#pragma unroll
                for (int m = 0; m < HH; ++m) {
                    piA = fmaf(hvA[m], wi[m], piA);
                    pfA = fmaf(hvA[m], wf[m], pfA);
                    pgA = fmaf(hvA[m], wg[m], pgA);
                    poA = fmaf(hvA[m], wo[m], poA);
                    piB = fmaf(hvB[m], wi[m], piB);
                    pfB = fmaf(hvB[m], wf[m], pfB);
                    pgB = fmaf(hvB[m], wg[m], pgB);
                    poB = fmaf(hvB[m], wo[m], poB);
                }
                float giA = fmaf(tanhap(piA), 0.5f, 0.5f);
                float gfA = fmaf(tanhap(pfA), 0.5f, 0.5f);
                float ggA = tanhap(pgA);
                float goAa = fmaf(tanhap(poA), 0.5f, 0.5f);
                float giB = fmaf(tanhap(piB), 0.5f, 0.5f);
                float gfB = fmaf(tanhap(pfB), 0.5f, 0.5f);
                float ggB = tanhap(pgB);
                float goBa = fmaf(tanhap(poB), 0.5f, 0.5f);
                cA = fmaf(gfA, cA, giA * ggA);
                cB = fmaf(gfB, cB, giB * ggB);
                hA = goAa * tanhap(cA);
                hB = goBa * tanhap(cB);
#pragma unroll
                for (int m = 0; m < HH; ++m) {
                    hvA[m] = __shfl_sync(0xffffffffu, hA, base + m);
                    hvB[m] = __shfl_sync(0xffffffffu, hB, base + m);
                }
            }
        }
    }

    if (j0 < HH) {
        float aA = b_fc[j], aB = b_fc[j];
#pragma unroll
        for (int m = 0; m < HH; ++m) {
            aA = fmaf(fmaxf(hvA[m], 0.0f), w_fc[j * HH + m], aA);
            aB = fmaf(fmaxf(hvB[m], 0.0f), w_fc[j * HH + m], aB);
        }
        out[(size_t)seqA * HH + j] = aA;
        out[(size_t)seqB * HH + j] = aB;
    }
}

extern "C" void kernel_launch(void* const* d_in, const int* in_sizes, int n_in,
                              void* d_out, int out_size) {
    const float* x    = (const float*)d_in[0];
    const float* w_ih = (const float*)d_in[1];
    const float* w_hh = (const float*)d_in[2];
    const float* b_ih = (const float*)d_in[3];
    const float* b_hh = (const float*)d_in[4];
    const float* w_fc = (const float*)d_in[5];
    const float* b_fc = (const float*)d_in[6];

    zero_flags<<<GEMM_CTAS / 256, 256>>>();
    cudaFuncSetAttribute(fused, cudaFuncAttributeMaxDynamicSharedMemorySize, SM_TOT);
    fused<<<LSTM_CTAS + GEMM_CTAS, THR, SM_TOT>>>(
        x, w_ih, b_ih, b_hh, w_hh, w_fc, b_fc, (float*)d_out);
}

// round 14
// speedup vs baseline: 1.1075x; 1.1075x over previous
#include <cuda_runtime.h>
#include <cuda_fp16.h>
#include <cstdint>

#define BB 2048
#define TT 512
#define DD 178
#define HH 5
#define NG 20
#define THR 128
#define LSTM_CTAS 64
#define GEMM_CTAS 1024
#define CHUNK_BYTES (64 * DD * 4)       // 45568  (64 rows)

typedef unsigned long long ull;

// fp16 gate pre-activations [b][t][j][i,f,g,o]; bias folded; i,f,o pre-scaled 0.5
__device__ __half g_xg[(size_t)BB * TT * NG];
__device__ int g_flag[GEMM_CTAS];

#define SO_TMA0 0
#define SO_TMA1 8
#define SO_BF   16                       // 18432 B
#define SO_S0   19456                    // 1024-aligned
#define SO_S1   (19456 + CHUNK_BYTES)    // 65024
#define SM_TOT  (SO_S1 + CHUNK_BYTES)    // 110592 -> 2 CTAs/SM

__device__ __forceinline__ uint32_t bf2(float hi, float lo) {
    uint32_t r; asm("cvt.rn.bf16x2.f32 %0, %1, %2;" : "=r"(r) : "f"(hi), "f"(lo)); return r;
}
__device__ __forceinline__ uint32_t h2pack(float lo, float hi) {
    uint32_t r; asm("cvt.rn.f16x2.f32 %0, %1, %2;" : "=r"(r) : "f"(hi), "f"(lo)); return r;
}
__device__ __forceinline__ void cvt_hl(float vx, float vy, uint32_t& h, uint32_t& l) {
    h = bf2(vy, vx);
    float hx = __uint_as_float(h << 16);
    float hy = __uint_as_float(h & 0xffff0000u);
    l = bf2(vy - hy, vx - hx);
}
__device__ __forceinline__ void mma16816(float& d0, float& d1, float& d2, float& d3,
                                         uint32_t a0, uint32_t a1, uint32_t a2, uint32_t a3,
                                         uint32_t b0, uint32_t b1) {
    asm volatile("mma.sync.aligned.m16n8k16.row.col.f32.bf16.bf16.f32 "
                 "{%0,%1,%2,%3}, {%4,%5,%6,%7}, {%8,%9}, {%0,%1,%2,%3};"
                 : "+f"(d0), "+f"(d1), "+f"(d2), "+f"(d3)
                 : "r"(a0), "r"(a1), "r"(a2), "r"(a3), "r"(b0), "r"(b1));
}
__device__ __forceinline__ float tanhap(float xv) {
    float r; asm("tanh.approx.f32 %0, %1;" : "=f"(r) : "f"(xv)); return r;
}
__device__ __forceinline__ void mbar_wait(uint32_t mbar, uint32_t parity) {
    asm volatile(
        "{\n\t.reg .pred P;\nW%=:\n\t"
        "mbarrier.try_wait.parity.acquire.cta.shared::cta.b64 P, [%0], %1, 0x989680;\n\t"
        "@P bra D%=;\n\tbra W%=;\nD%=:\n\t}"
        :: "r"(mbar), "r"(parity) : "memory");
}
__device__ __forceinline__ int ld_acq(const int* p) {
    int v; asm volatile("ld.acquire.gpu.global.u32 %0, [%1];" : "=r"(v) : "l"(p)); return v;
}

extern "C" __global__ void zero_flags() {
    g_flag[blockIdx.x * 256 + threadIdx.x] = 0;
}

// ===========================================================================
// Fused kernel, 128-thread CTAs (2 resident/SM). bid < 64: LSTM consumers
// (4 warps each). bid >= 64: GEMM producers: 16 chunks of 64 rows (1 seq x
// 64 timesteps each), 4 warps x 16 rows, full-K 12 ktiles, 3 MMA passes
// (Ah*Bh + Ah*Bl + Al*Bh) — R10 precision scheme.
// ===========================================================================
extern "C" __global__ void __launch_bounds__(THR, 2)
fused(const float* __restrict__ x, const float* __restrict__ w_ih,
      const float* __restrict__ b_ih, const float* __restrict__ b_hh,
      const float* __restrict__ w_hh, const float* __restrict__ w_fc,
      const float* __restrict__ b_fc, float* __restrict__ out) {
    extern __shared__ char smem[];
    const int tid = threadIdx.x;
    const int lane = tid & 31;

    if (blockIdx.x >= LSTM_CTAS) {
        // ------------------- GEMM producer -------------------
        const int c = blockIdx.x - LSTM_CTAS;
        const int krange = c >> 7;            // t-range (64 steps)
        const int bg = c & 127;               // b-group (16 sequences)
        const int tbase = krange * 64;

        const uint32_t smb = (uint32_t)__cvta_generic_to_shared(smem);
        const uint32_t mbar0 = smb + SO_TMA0, mbar1 = smb + SO_TMA1;
        const int warp = tid >> 5;
        const int gq = lane >> 2, tq = lane & 3;
        const int r1 = warp * 16 + gq;        // row 0..63 within chunk

        uint2* bfrag = (uint2*)(smem + SO_BF);

        for (int idx = tid; idx < 12 * 3 * 32; idx += THR) {
            int l = idx & 31, nt = (idx >> 5) % 3, kt = idx / 96;
            int n = nt * 8 + (l >> 2);
            int k = kt * 16 + 2 * (l & 3);
            float w0 = 0, w1 = 0, w2 = 0, w3 = 0;
            if (n < NG) {
                int cc = n & 3, j = n >> 2;
                float s = (cc == 2) ? 1.0f : 0.5f;
                const float* wr = w_ih + (cc * 5 + j) * DD;
                if (k     < DD) w0 = s * wr[k];
                if (k + 1 < DD) w1 = s * wr[k + 1];
                if (k + 8 < DD) w2 = s * wr[k + 8];
                if (k + 9 < DD) w3 = s * wr[k + 9];
            }
            uint32_t b0h, b0l, b1h, b1l;
            cvt_hl(w0, w1, b0h, b0l);
            cvt_hl(w2, w3, b1h, b1l);
            bfrag[(((kt * 3 + nt) * 2 + 0) * 32) + l] = make_uint2(b0h, b1h);
            bfrag[(((kt * 3 + nt) * 2 + 1) * 32) + l] = make_uint2(b0l, b1l);
        }

        float bias0[3], bias1[3];
#pragma unroll
        for (int nt = 0; nt < 3; ++nt) {
            int n0 = nt * 8 + 2 * tq;
            bias0[nt] = bias1[nt] = 0.0f;
            if (n0 < NG) {
                int cc = n0 & 3, j = n0 >> 2;
                float s = (cc == 2) ? 1.0f : 0.5f;
                bias0[nt] = s * (b_ih[cc * 5 + j] + b_hh[cc * 5 + j]);
                cc = (n0 + 1) & 3; j = (n0 + 1) >> 2;
                s = (cc == 2) ? 1.0f : 0.5f;
                bias1[nt] = s * (b_ih[cc * 5 + j] + b_hh[cc * 5 + j]);
            }
        }

        if (tid == 0) {
            asm volatile("mbarrier.init.shared.b64 [%0], 1;" :: "r"(mbar0));
            asm volatile("mbarrier.init.shared.b64 [%0], 1;" :: "r"(mbar1));
            asm volatile("fence.proxy.async.shared::cta;" ::: "memory");
        }
        __syncthreads();

        ull pol;
        asm("createpolicy.fractional.L2::evict_first.b64 %0, 1.0;" : "=l"(pol));

        // chunk ch = sequence bg*16+ch, timesteps [tbase, tbase+64)
        auto issue = [&](int ch) {
            uint32_t mb  = (ch & 1) ? mbar1 : mbar0;
            uint32_t dst = smb + ((ch & 1) ? SO_S1 : SO_S0);
            int b = bg * 16 + ch;
            const char* src = (const char*)(x + ((size_t)b * TT + tbase) * DD);
            asm volatile("mbarrier.arrive.expect_tx.shared.b64 _, [%0], %1;"
                         :: "r"(mb), "r"((uint32_t)CHUNK_BYTES));
            asm volatile(
                "cp.async.bulk.shared::cluster.global.mbarrier::complete_tx::bytes"
                ".L2::cache_hint [%0], [%1], %2, [%3], %4;"
                :: "r"(dst), "l"(src), "r"((uint32_t)CHUNK_BYTES), "r"(mb), "l"(pol)
                : "memory");
        };
        if (tid == 0) { issue(0); issue(1); }

        for (int ch = 0; ch < 16; ++ch) {
            mbar_wait((ch & 1) ? mbar1 : mbar0, (uint32_t)((ch >> 1) & 1));
            const float* pr =
                (const float*)(smem + ((ch & 1) ? SO_S1 : SO_S0)) + r1 * DD;

            float d[3][4];
#pragma unroll
            for (int nt = 0; nt < 3; ++nt) {
                d[nt][0] = bias0[nt]; d[nt][1] = bias1[nt];
                d[nt][2] = bias0[nt]; d[nt][3] = bias1[nt];
            }
#pragma unroll
            for (int kt = 0; kt < 12; ++kt) {
                int k0 = kt * 16 + 2 * tq;
                bool v0 = (k0 <= DD - 2);
                bool v2 = (k0 + 8 <= DD - 2);
                float2 z = make_float2(0.0f, 0.0f);
                float2 A0 = v0 ? *(const float2*)(pr + k0)              : z;
                float2 A1 = v0 ? *(const float2*)(pr + 8 * DD + k0)     : z;
                float2 A2 = v2 ? *(const float2*)(pr + k0 + 8)          : z;
                float2 A3 = v2 ? *(const float2*)(pr + 8 * DD + k0 + 8) : z;
                uint32_t ah0, al0, ah1, al1, ah2, al2, ah3, al3;
                cvt_hl(A0.x, A0.y, ah0, al0);
                cvt_hl(A1.x, A1.y, ah1, al1);
                cvt_hl(A2.x, A2.y, ah2, al2);
                cvt_hl(A3.x, A3.y, ah3, al3);
#pragma unroll
                for (int nt = 0; nt < 3; ++nt) {
                    uint2 BH = bfrag[(((kt * 3 + nt) * 2 + 0) * 32) + lane];
                    uint2 BL = bfrag[(((kt * 3 + nt) * 2 + 1) * 32) + lane];
                    mma16816(d[nt][0], d[nt][1], d[nt][2], d[nt][3],
                             ah0, ah1, ah2, ah3, BH.x, BH.y);
                    mma16816(d[nt][0], d[nt][1], d[nt][2], d[nt][3],
                             ah0, ah1, ah2, ah3, BL.x, BL.y);
                    mma16816(d[nt][0], d[nt][1], d[nt][2], d[nt][3],
                             al0, al1, al2, al3, BH.x, BH.y);
                }
            }
            __syncthreads();                 // staging reads done
            if (tid == 0 && ch + 2 < 16) issue(ch + 2);

            int b = bg * 16 + ch;
            int t = tbase + r1;
            size_t grow = (size_t)b * TT + t;
#pragma unroll
            for (int nt = 0; nt < 3; ++nt) {
                int n0 = nt * 8 + 2 * tq;
                if (n0 < NG) {
                    *(uint32_t*)((char*)g_xg + grow * 40 + n0 * 2) =
                        h2pack(d[nt][0], d[nt][1]);
                    *(uint32_t*)((char*)g_xg + (grow + 8) * 40 + n0 * 2) =
                        h2pack(d[nt][2], d[nt][3]);
                }
            }
        }
        __threadfence();
        __syncthreads();
        if (tid == 0)
            asm volatile("st.release.gpu.global.u32 [%0], %1;"
                         :: "l"(&g_flag[c]), "r"(1) : "memory");
        return;
    }

    // ------------------- LSTM consumer (R10 layout, 4 warps/CTA) -------------------
    const int w    = blockIdx.x * 4 + (tid >> 5);   // 0..255
    const int j0   = lane & 7;
    const int j    = (j0 < HH) ? j0 : 0;
    const int gidx = w * 4 + (lane >> 3);
    const int seqA = 2 * gidx, seqB = seqA + 1;
    const int bgf  = w >> 1;

    float wi[HH], wf[HH], wg[HH], wo[HH];
#pragma unroll
    for (int m = 0; m < HH; ++m) {
        wi[m] = 0.5f * w_hh[j * HH + m];
        wf[m] = 0.5f * w_hh[(HH + j) * HH + m];
        wg[m] =        w_hh[(2 * HH + j) * HH + m];
        wo[m] = 0.5f * w_hh[(3 * HH + j) * HH + m];
    }

    const uint2* gpA = (const uint2*)((const char*)g_xg + (size_t)seqA * TT * 40) + j;
    const uint2* gpB = (const uint2*)((const char*)g_xg + (size_t)seqB * TT * 40) + j;

    float cA = 0.0f, hA = 0.0f, cB = 0.0f, hB = 0.0f;
    float hvA[HH], hvB[HH];
#pragma unroll
    for (int m = 0; m < HH; ++m) { hvA[m] = 0.0f; hvB[m] = 0.0f; }
    const int base = lane & ~7;

    for (int k = 0; k < 8; ++k) {
        const int* fp = &g_flag[k * 128 + bgf];
        if (lane == 0) { while (ld_acq(fp) == 0) __nanosleep(128); }
        __syncwarp();
        (void)ld_acq(fp);

        const int t0 = k * 64;
        uint2 rA[8], rB[8];
#pragma unroll
        for (int p = 0; p < 8; ++p) {
            rA[p] = gpA[(size_t)(t0 + p) * 5];
            rB[p] = gpB[(size_t)(t0 + p) * 5];
        }

        for (int p0 = 0; p0 < 64; p0 += 8) {
#pragma unroll
            for (int pp = 0; pp < 8; ++pp) {
                uint2 curA = rA[pp], curB = rB[pp];
                if (p0 + pp + 8 < 64) {
                    int tn = t0 + p0 + pp + 8;
                    rA[pp] = gpA[(size_t)tn * 5];
                    rB[pp] = gpB[(size_t)tn * 5];
                }
                float2 ifA = __half22float2(*(const __half2*)&curA.x);
                float2 goA = __half22float2(*(const __half2*)&curA.y);
                float2 ifB = __half22float2(*(const __half2*)&curB.x);
                float2 goB = __half22float2(*(const __half2*)&curB.y);

                float piA = ifA.x, pfA = ifA.y, pgA = goA.x, poA = goA.y;
                float piB = ifB.x, pfB = ifB.y, pgB = goB.x, poB = goB.y;
#pragma unroll
                for (int m = 0; m < HH; ++m) {
                    piA = fmaf(hvA[m], wi[m], piA);
                    pfA = fmaf(hvA[m], wf[m], pfA);
                    pgA = fmaf(hvA[m], wg[m], pgA);
                    poA = fmaf(hvA[m], wo[m], poA);
                    piB = fmaf(hvB[m], wi[m], piB);
                    pfB = fmaf(hvB[m], wf[m], pfB);
                    pgB = fmaf(hvB[m], wg[m], pgB);
                    poB = fmaf(hvB[m], wo[m], poB);
                }
                float giA = fmaf(tanhap(piA), 0.5f, 0.5f);
                float gfA = fmaf(tanhap(pfA), 0.5f, 0.5f);
                float ggA = tanhap(pgA);
                float goAa = fmaf(tanhap(poA), 0.5f, 0.5f);
                float giB = fmaf(tanhap(piB), 0.5f, 0.5f);
                float gfB = fmaf(tanhap(pfB), 0.5f, 0.5f);
                float ggB = tanhap(pgB);
                float goBa = fmaf(tanhap(poB), 0.5f, 0.5f);
                cA = fmaf(gfA, cA, giA * ggA);
                cB = fmaf(gfB, cB, giB * ggB);
                hA = goAa * tanhap(cA);
                hB = goBa * tanhap(cB);
#pragma unroll
                for (int m = 0; m < HH; ++m) {
                    hvA[m] = __shfl_sync(0xffffffffu, hA, base + m);
                    hvB[m] = __shfl_sync(0xffffffffu, hB, base + m);
                }
            }
        }
    }

    if (j0 < HH) {
        float aA = b_fc[j], aB = b_fc[j];
#pragma unroll
        for (int m = 0; m < HH; ++m) {
            aA = fmaf(fmaxf(hvA[m], 0.0f), w_fc[j * HH + m], aA);
            aB = fmaf(fmaxf(hvB[m], 0.0f), w_fc[j * HH + m], aB);
        }
        out[(size_t)seqA * HH + j] = aA;
        out[(size_t)seqB * HH + j] = aB;
    }
}

extern "C" void kernel_launch(void* const* d_in, const int* in_sizes, int n_in,
                              void* d_out, int out_size) {
    const float* x    = (const float*)d_in[0];
    const float* w_ih = (const float*)d_in[1];
    const float* w_hh = (const float*)d_in[2];
    const float* b_ih = (const float*)d_in[3];
    const float* b_hh = (const float*)d_in[4];
    const float* w_fc = (const float*)d_in[5];
    const float* b_fc = (const float*)d_in[6];

    zero_flags<<<GEMM_CTAS / 256, 256>>>();
    cudaFuncSetAttribute(fused, cudaFuncAttributeMaxDynamicSharedMemorySize, SM_TOT);
    fused<<<LSTM_CTAS + GEMM_CTAS, THR, SM_TOT>>>(
        x, w_ih, b_ih, b_hh, w_hh, w_fc, b_fc, (float*)d_out);
}